// round 8
// baseline (speedup 1.0000x reference)
#include <cuda_runtime.h>
#include <cuda_bf16.h>
#include <cstdint>
#include <cmath>

#define HIDN 1024
#define EMBD 1024
#define BATCH 256
#define SEQL 128
#define NCLS 32000
#define NG   4096   /* 4*HIDN, gate-interleaved: n = 4*j + g */

#define BM 128
#define BN 64
#define BK 16
#define AS 20
#define BSS 20
#define GS 68
#define VSTR 516
#define ASTR 36          /* steps A-stage stride (u32) */
#define STG_A (128 * ASTR)

#define NCTA 128
#define PTHREADS 512

// ---------------- device scratch (no allocations allowed) ----------------
static __device__ unsigned g_Ub[NG * (HIDN / 2)];            // 8 MB interleaved U, bf16x2
static __device__ unsigned g_Vb[NG * (HIDN / 2)];            // 8 MB interleaved V, bf16x2
static __device__ unsigned g_Eb[(size_t)NCLS * (EMBD / 2)];  // 64 MB emb, bf16x2
static __device__ float    g_ball[NG];
static __device__ float    g_Zin[(size_t)SEQL * BATCH * NG]; // 512 MB input-side gates
static __device__ float    g_h[2][BATCH * HIDN];             // fp32 h (final proj reads [0])
static __device__ unsigned g_hb[2][BATCH * (HIDN / 2)];      // bf16x2 h ping-pong
static __device__ float    g_c[BATCH * HIDN];
static __device__ unsigned g_bar;                            // grid barrier

// ---------------- helpers ----------------
__device__ __forceinline__ float f2tf32(float x) {
    uint32_t r;
    asm("cvt.rna.tf32.f32 %0, %1;" : "=r"(r) : "f"(x));
    return __uint_as_float(r);
}
__device__ __forceinline__ unsigned pack_bf2(float a, float b) {
    __nv_bfloat162 v = __floats2bfloat162_rn(a, b);
    return *reinterpret_cast<unsigned*>(&v);
}
__device__ __forceinline__ float fsig(float x) {
    return __fdividef(1.f, 1.f + __expf(-x));
}
__device__ __forceinline__ void mma_bf16(float* acc, const unsigned* a, const unsigned* b) {
    asm volatile(
        "mma.sync.aligned.m16n8k16.row.col.f32.bf16.bf16.f32 "
        "{%0,%1,%2,%3}, {%4,%5,%6,%7}, {%8,%9}, {%0,%1,%2,%3};"
        : "+f"(acc[0]), "+f"(acc[1]), "+f"(acc[2]), "+f"(acc[3])
        : "r"(a[0]), "r"(a[1]), "r"(a[2]), "r"(a[3]), "r"(b[0]), "r"(b[1]));
}

// ---------------- pack: interleave U/V (bf16), biases, init state ----------------
__global__ void pack_kernel(const float* __restrict__ Ui, const float* __restrict__ Vi, const float* __restrict__ bi,
                            const float* __restrict__ Uf, const float* __restrict__ Vf, const float* __restrict__ bf,
                            const float* __restrict__ Uc, const float* __restrict__ Vc, const float* __restrict__ bc,
                            const float* __restrict__ Uo, const float* __restrict__ Vo, const float* __restrict__ bo,
                            const float* __restrict__ h0, const float* __restrict__ c0)
{
    int idx = blockIdx.x * blockDim.x + threadIdx.x;
    if (idx >= NG * (HIDN / 2)) return;
    if (idx == 0) g_bar = 0u;
    int n = idx >> 9;
    int k2 = idx & 511;
    int j = n >> 2, g = n & 3;
    const float *U, *V, *bb;
    if (g == 0)      { U = Ui; V = Vi; bb = bi; }
    else if (g == 1) { U = Uf; V = Vf; bb = bf; }
    else if (g == 2) { U = Uc; V = Vc; bb = bc; }
    else             { U = Uo; V = Vo; bb = bo; }
    const float* Up = U + (size_t)j * HIDN + 2 * k2;
    const float* Vp = V + (size_t)j * HIDN + 2 * k2;
    g_Ub[idx] = pack_bf2(Up[0], Up[1]);
    g_Vb[idx] = pack_bf2(Vp[0], Vp[1]);
    if (k2 == 0) g_ball[n] = bb[j];
    if (idx < BATCH * (HIDN / 2)) {
        g_hb[0][idx] = pack_bf2(h0[2 * idx], h0[2 * idx + 1]);
        float2 hv; hv.x = h0[2 * idx]; hv.y = h0[2 * idx + 1];
        *(float2*)&g_h[0][2 * idx] = hv;
        float2 cv; cv.x = c0[2 * idx]; cv.y = c0[2 * idx + 1];
        *(float2*)&g_c[2 * idx] = cv;
    }
}

__global__ void pack_emb_kernel(const float* __restrict__ emb)
{
    size_t idx = (size_t)blockIdx.x * blockDim.x + threadIdx.x;
    if (idx >= (size_t)NCLS * (EMBD / 2)) return;
    g_Eb[idx] = pack_bf2(emb[2 * idx], emb[2 * idx + 1]);
}

// ---------------- bf16 input GEMM: Zin = gather(emb,X) @ Uall^T + ball ----------------
// grid (32, 256), 256 threads, CTA tile 128x128, warp tile 64x32
__global__ __launch_bounds__(256, 2)
void input_gemm_kernel(const int* __restrict__ Xids)
{
    const int tid  = threadIdx.x;
    const int lane = tid & 31;
    const int warp = tid >> 5;
    const int wm = (warp >> 2) * 64;
    const int wn = (warp & 3) * 32;
    const int n0 = blockIdx.x * 128;
    const int m0 = blockIdx.y * 128;

    __shared__ unsigned smA[2][128 * 20];
    __shared__ unsigned smB[2][128 * 20];
    __shared__ int vrow[128];

    if (tid < 128) {
        int r = m0 + tid;
        vrow[tid] = Xids[(r & 255) * SEQL + (r >> 8)];
    }
    __syncthreads();

    const int kcol  = (tid & 3) * 4;
    const int ldrow = tid >> 2;

    const unsigned* ap0 = g_Eb + (size_t)vrow[ldrow] * 512 + kcol;
    const unsigned* ap1 = g_Eb + (size_t)vrow[ldrow + 64] * 512 + kcol;
    const unsigned* bp0 = g_Ub + (size_t)(n0 + ldrow) * 512 + kcol;
    const unsigned* bp1 = g_Ub + (size_t)(n0 + ldrow + 64) * 512 + kcol;

    float acc[4][4][4];
#pragma unroll
    for (int a = 0; a < 4; a++)
#pragma unroll
        for (int b_ = 0; b_ < 4; b_++)
#pragma unroll
            for (int c_ = 0; c_ < 4; c_++) acc[a][b_][c_] = 0.f;

    uint4 a0 = *(const uint4*)ap0;
    uint4 a1 = *(const uint4*)ap1;
    uint4 b0 = *(const uint4*)bp0;
    uint4 b1 = *(const uint4*)bp1;
    *(uint4*)&smA[0][ldrow * 20 + kcol]        = a0;
    *(uint4*)&smA[0][(ldrow + 64) * 20 + kcol] = a1;
    *(uint4*)&smB[0][ldrow * 20 + kcol]        = b0;
    *(uint4*)&smB[0][(ldrow + 64) * 20 + kcol] = b1;
    __syncthreads();

    for (int kc = 0; kc < 32; kc++) {
        const int cur = kc & 1;
        if (kc + 1 < 32) {
            a0 = *(const uint4*)(ap0 + (kc + 1) * 16);
            a1 = *(const uint4*)(ap1 + (kc + 1) * 16);
            b0 = *(const uint4*)(bp0 + (kc + 1) * 16);
            b1 = *(const uint4*)(bp1 + (kc + 1) * 16);
        }
#pragma unroll
        for (int ks = 0; ks < 2; ks++) {
            unsigned af[4][4], bfr[4][2];
#pragma unroll
            for (int mt = 0; mt < 4; mt++) {
                const unsigned* ap = &smA[cur][(wm + mt * 16 + (lane >> 2)) * 20 + ks * 8 + (lane & 3)];
                af[mt][0] = ap[0]; af[mt][1] = ap[8 * 20]; af[mt][2] = ap[4]; af[mt][3] = ap[8 * 20 + 4];
            }
#pragma unroll
            for (int nt = 0; nt < 4; nt++) {
                const unsigned* bp = &smB[cur][(wn + nt * 8 + (lane >> 2)) * 20 + ks * 8 + (lane & 3)];
                bfr[nt][0] = bp[0]; bfr[nt][1] = bp[4];
            }
#pragma unroll
            for (int mt = 0; mt < 4; mt++)
#pragma unroll
                for (int nt = 0; nt < 4; nt++)
                    mma_bf16(acc[mt][nt], af[mt], bfr[nt]);
        }
        if (kc + 1 < 32) {
            const int nxt = (kc + 1) & 1;
            *(uint4*)&smA[nxt][ldrow * 20 + kcol]        = a0;
            *(uint4*)&smA[nxt][(ldrow + 64) * 20 + kcol] = a1;
            *(uint4*)&smB[nxt][ldrow * 20 + kcol]        = b0;
            *(uint4*)&smB[nxt][(ldrow + 64) * 20 + kcol] = b1;
        }
        __syncthreads();
    }

#pragma unroll
    for (int mt = 0; mt < 4; mt++) {
#pragma unroll
        for (int nt = 0; nt < 4; nt++) {
            int r = m0 + wm + mt * 16 + (lane >> 2);
            int cidx = n0 + wn + nt * 8 + (lane & 3) * 2;
            float2 bv = *(const float2*)&g_ball[cidx];
            float2 o0; o0.x = acc[mt][nt][0] + bv.x; o0.y = acc[mt][nt][1] + bv.y;
            float2 o1; o1.x = acc[mt][nt][2] + bv.x; o1.y = acc[mt][nt][3] + bv.y;
            *(float2*)&g_Zin[(size_t)r * NG + cidx] = o0;
            *(float2*)&g_Zin[(size_t)(r + 8) * NG + cidx] = o1;
        }
    }
}

// ---------------- persistent recurrent kernel: 512 threads, 16 warps (4/SMSP) ----------------
// warp grid 4m x 4n, warp tile 32x16, K-chunk 32 half2 (16 iterations)
#define SMEM_P_BYTES ((64 * VSTR) * 4 + 2 * STG_A * 4)

__global__ __launch_bounds__(PTHREADS, 1)
void lstm_persistent_kernel()
{
    extern __shared__ unsigned smem[];
    unsigned* smV = smem;
    unsigned* smA = smem + 64 * VSTR;
    float*    smG = (float*)(smem + 64 * VSTR);

    const int tid  = threadIdx.x;
    const int lane = tid & 31;
    const int warp = tid >> 5;          // 0..15
    const int wm = (warp >> 2) * 32;    // 4 m-warps x 32 rows
    const int wn = (warp & 3) * 16;     // 4 n-warps x 16 cols
    const int bid = blockIdx.x;
    const int m0  = (bid & 1) * 128;
    const int nsl = bid >> 1;
    const int n0  = nsl * 64;

    for (int i = tid; i < 64 * 128; i += PTHREADS) {
        int n = i >> 7, k4 = (i & 127) * 4;
        *(uint4*)&smV[n * VSTR + k4] = *(const uint4*)&g_Vb[(size_t)(n0 + n) * 512 + k4];
    }

    // c slice in registers: 1024 items / 512 threads = 2 per thread
    float creg[2][2];
#pragma unroll
    for (int it = 0; it < 2; it++) {
        int idx = tid + it * PTHREADS;
        int lr = idx >> 3, jp = idx & 7;
        float2 cv = *(const float2*)&g_c[(m0 + lr) * HIDN + nsl * 16 + jp * 2];
        creg[it][0] = cv.x; creg[it][1] = cv.y;
    }

    const int kc8   = (tid & 3) * 8;    // staging: 4 threads x 8 half2-units cover a 32-unit row
    const int ldrow = tid >> 2;         // 0..127
    __syncthreads();

    for (int t = 0; t < SEQL; t++) {
        // prefetch this step's Zin slice early (hidden behind the GEMM)
        float4 zpre[2][2];
#pragma unroll
        for (int it = 0; it < 2; it++) {
            int idx = tid + it * PTHREADS;
            int lr = idx >> 3, jp = idx & 7;
            size_t zb = ((size_t)t * BATCH + m0 + lr) * NG + n0 + jp * 8;
            zpre[it][0] = *(const float4*)&g_Zin[zb];
            zpre[it][1] = *(const float4*)&g_Zin[zb + 4];
        }

        const unsigned* hin = g_hb[t & 1];
        const unsigned* arp = hin + (size_t)(m0 + ldrow) * 512 + kc8;

        float acc[2][2][4];
#pragma unroll
        for (int a = 0; a < 2; a++)
#pragma unroll
            for (int b_ = 0; b_ < 2; b_++)
#pragma unroll
                for (int c_ = 0; c_ < 4; c_++) acc[a][b_][c_] = 0.f;

        uint4 a00 = *(const uint4*)arp;
        uint4 a01 = *(const uint4*)(arp + 4);
        *(uint4*)&smA[ldrow * ASTR + kc8]     = a00;
        *(uint4*)&smA[ldrow * ASTR + kc8 + 4] = a01;
        __syncthreads();

        for (int kc = 0; kc < 16; kc++) {
            const int cur = kc & 1;
            if (kc + 1 < 16) {
                a00 = *(const uint4*)(arp + (kc + 1) * 32);
                a01 = *(const uint4*)(arp + (kc + 1) * 32 + 4);
            }
            const unsigned* As = smA + cur * STG_A;
#pragma unroll
            for (int ks = 0; ks < 4; ks++) {
                unsigned af[2][4], bfr[2][2];
#pragma unroll
                for (int mtw = 0; mtw < 2; mtw++) {
                    const unsigned* ap = &As[(wm + mtw * 16 + (lane >> 2)) * ASTR + ks * 8 + (lane & 3)];
                    af[mtw][0] = ap[0]; af[mtw][1] = ap[8 * ASTR]; af[mtw][2] = ap[4]; af[mtw][3] = ap[8 * ASTR + 4];
                }
#pragma unroll
                for (int ntw = 0; ntw < 2; ntw++) {
                    const unsigned* bp = &smV[(wn + ntw * 8 + (lane >> 2)) * VSTR + kc * 32 + ks * 8 + (lane & 3)];
                    bfr[ntw][0] = bp[0]; bfr[ntw][1] = bp[4];
                }
#pragma unroll
                for (int mtw = 0; mtw < 2; mtw++)
#pragma unroll
                    for (int ntw = 0; ntw < 2; ntw++)
                        mma_bf16(acc[mtw][ntw], af[mtw], bfr[ntw]);
            }
            if (kc + 1 < 16) {
                unsigned* Ad = smA + ((kc + 1) & 1) * STG_A;
                *(uint4*)&Ad[ldrow * ASTR + kc8]     = a00;
                *(uint4*)&Ad[ldrow * ASTR + kc8 + 4] = a01;
            }
            __syncthreads();
        }

        // accum -> smem gate tile (overlays A staging; all mma reads done)
#pragma unroll
        for (int mtw = 0; mtw < 2; mtw++)
#pragma unroll
            for (int ntw = 0; ntw < 2; ntw++) {
                int lr = wm + mtw * 16 + (lane >> 2);
                int lc = wn + ntw * 8 + (lane & 3) * 2;
                smG[lr * GS + lc]           = acc[mtw][ntw][0];
                smG[lr * GS + lc + 1]       = acc[mtw][ntw][1];
                smG[(lr + 8) * GS + lc]     = acc[mtw][ntw][2];
                smG[(lr + 8) * GS + lc + 1] = acc[mtw][ntw][3];
            }
        __syncthreads();

        // fused LSTM cell (c in registers)
        unsigned* hbout = g_hb[(t & 1) ^ 1];
#pragma unroll
        for (int it = 0; it < 2; it++) {
            int idx = tid + it * PTHREADS;
            int lr = idx >> 3, jp = idx & 7;
            int m = m0 + lr;
            float4 z0 = zpre[it][0];
            float4 z1 = zpre[it][1];
            const float* Gp = &smG[lr * GS + jp * 8];

            float i0 = fsig(Gp[0] + z0.x);
            float f0 = fsig(Gp[1] + z0.y);
            float g0 = tanhf(Gp[2] + z0.z);
            float o0 = fsig(Gp[3] + z0.w);
            float i1 = fsig(Gp[4] + z1.x);
            float f1 = fsig(Gp[5] + z1.y);
            float g1 = tanhf(Gp[6] + z1.z);
            float o1 = fsig(Gp[7] + z1.w);

            float cn0 = f0 * creg[it][0] + i0 * g0;
            float cn1 = f1 * creg[it][1] + i1 * g1;
            creg[it][0] = cn0; creg[it][1] = cn1;

            float h0v = o0 * tanhf(cn0);
            float h1v = o1 * tanhf(cn1);
            hbout[m * 512 + nsl * 8 + jp] = pack_bf2(h0v, h1v);
            if (t == SEQL - 1) {
                float2 hf; hf.x = h0v; hf.y = h1v;
                *(float2*)&g_h[0][m * HIDN + nsl * 16 + jp * 2] = hf;
            }
        }

        if (t < SEQL - 1) {
            __syncthreads();
            if (tid == 0) {
                __threadfence();
                atomicAdd(&g_bar, 1u);
                const unsigned target = (unsigned)NCTA * (t + 1);
                unsigned v;
                do {
                    asm volatile("ld.acquire.gpu.u32 %0, [%1];"
                                 : "=r"(v) : "l"(&g_bar) : "memory");
                } while (v < target);
            }
            __syncthreads();
        }
    }
}

// ---------------- tf32 output projection: out = h_final @ W^T + b ----------------
__global__ __launch_bounds__(128)
void out_gemm_kernel(const float* __restrict__ W,
                     const float* __restrict__ biasp,
                     float* __restrict__ Cout)
{
    const int tid  = threadIdx.x;
    const int lane = tid & 31;
    const int warp = tid >> 5;
    const int wm = (warp >> 1) * 64;
    const int wn = (warp & 1) * 32;
    const int n0 = blockIdx.x * BN;
    const int m0 = blockIdx.y * BM;

    __shared__ struct { float A[2][BM * AS]; float B[2][BN * BSS]; } sm;

    const float* Ain = g_h[0];
    const int kcol  = (tid & 3) * 4;
    const int ldrow = tid >> 2;

    const float* arp[4];
#pragma unroll
    for (int i = 0; i < 4; i++)
        arp[i] = Ain + (size_t)(m0 + ldrow + 32 * i) * HIDN + kcol;
    const float* brp[2];
#pragma unroll
    for (int i = 0; i < 2; i++)
        brp[i] = W + (size_t)(n0 + ldrow + 32 * i) * HIDN + kcol;

    float4 areg[4], breg[2];
    float acc[4][4][4];
#pragma unroll
    for (int a = 0; a < 4; a++)
#pragma unroll
        for (int b_ = 0; b_ < 4; b_++)
#pragma unroll
            for (int c_ = 0; c_ < 4; c_++) acc[a][b_][c_] = 0.f;

#pragma unroll
    for (int i = 0; i < 4; i++) areg[i] = *(const float4*)(arp[i]);
#pragma unroll
    for (int i = 0; i < 2; i++) breg[i] = *(const float4*)(brp[i]);
#pragma unroll
    for (int i = 0; i < 4; i++) {
        float4 v = areg[i];
        v.x = f2tf32(v.x); v.y = f2tf32(v.y); v.z = f2tf32(v.z); v.w = f2tf32(v.w);
        *(float4*)&sm.A[0][(ldrow + 32 * i) * AS + kcol] = v;
    }
#pragma unroll
    for (int i = 0; i < 2; i++) {
        float4 v = breg[i];
        v.x = f2tf32(v.x); v.y = f2tf32(v.y); v.z = f2tf32(v.z); v.w = f2tf32(v.w);
        *(float4*)&sm.B[0][(ldrow + 32 * i) * BSS + kcol] = v;
    }
    __syncthreads();

    const int NCH = HIDN / BK;
    for (int kc = 0; kc < NCH; kc++) {
        int cur = kc & 1;
        if (kc + 1 < NCH) {
#pragma unroll
            for (int i = 0; i < 4; i++) areg[i] = *(const float4*)(arp[i] + (kc + 1) * BK);
#pragma unroll
            for (int i = 0; i < 2; i++) breg[i] = *(const float4*)(brp[i] + (kc + 1) * BK);
        }
#pragma unroll
        for (int k8 = 0; k8 < BK; k8 += 8) {
            uint32_t af[4][4], bfr[4][2];
#pragma unroll
            for (int mt = 0; mt < 4; mt++) {
                const float* ap = &sm.A[cur][(wm + mt * 16 + (lane >> 2)) * AS + k8 + (lane & 3)];
                af[mt][0] = __float_as_uint(ap[0]);
                af[mt][1] = __float_as_uint(ap[8 * AS]);
                af[mt][2] = __float_as_uint(ap[4]);
                af[mt][3] = __float_as_uint(ap[8 * AS + 4]);
            }
#pragma unroll
            for (int nt = 0; nt < 4; nt++) {
                const float* bp = &sm.B[cur][(wn + nt * 8 + (lane >> 2)) * BSS + k8 + (lane & 3)];
                bfr[nt][0] = __float_as_uint(bp[0]);
                bfr[nt][1] = __float_as_uint(bp[4]);
            }
#pragma unroll
            for (int mt = 0; mt < 4; mt++)
#pragma unroll
                for (int nt = 0; nt < 4; nt++)
                    asm volatile(
                        "mma.sync.aligned.m16n8k8.row.col.f32.tf32.tf32.f32 "
                        "{%0,%1,%2,%3}, {%4,%5,%6,%7}, {%8,%9}, {%0,%1,%2,%3};"
                        : "+f"(acc[mt][nt][0]), "+f"(acc[mt][nt][1]),
                          "+f"(acc[mt][nt][2]), "+f"(acc[mt][nt][3])
                        : "r"(af[mt][0]), "r"(af[mt][1]), "r"(af[mt][2]), "r"(af[mt][3]),
                          "r"(bfr[nt][0]), "r"(bfr[nt][1]));
        }
        if (kc + 1 < NCH) {
            int nxt = cur ^ 1;
#pragma unroll
            for (int i = 0; i < 4; i++) {
                float4 v = areg[i];
                v.x = f2tf32(v.x); v.y = f2tf32(v.y); v.z = f2tf32(v.z); v.w = f2tf32(v.w);
                *(float4*)&sm.A[nxt][(ldrow + 32 * i) * AS + kcol] = v;
            }
#pragma unroll
            for (int i = 0; i < 2; i++) {
                float4 v = breg[i];
                v.x = f2tf32(v.x); v.y = f2tf32(v.y); v.z = f2tf32(v.z); v.w = f2tf32(v.w);
                *(float4*)&sm.B[nxt][(ldrow + 32 * i) * BSS + kcol] = v;
            }
        }
        __syncthreads();
    }

#pragma unroll
    for (int mt = 0; mt < 4; mt++) {
#pragma unroll
        for (int nt = 0; nt < 4; nt++) {
            int r = m0 + wm + mt * 16 + (lane >> 2);
            int cidx = n0 + wn + nt * 8 + (lane & 3) * 2;
            float2 bv = *(const float2*)&biasp[cidx];
            float2 v0; v0.x = acc[mt][nt][0] + bv.x; v0.y = acc[mt][nt][1] + bv.y;
            float2 v1; v1.x = acc[mt][nt][2] + bv.x; v1.y = acc[mt][nt][3] + bv.y;
            *(float2*)&Cout[(size_t)r * NCLS + cidx] = v0;
            *(float2*)&Cout[(size_t)(r + 8) * NCLS + cidx] = v1;
        }
    }
}

// ---------------- launch ----------------
extern "C" void kernel_launch(void* const* d_in, const int* in_sizes, int n_in,
                              void* d_out, int out_size)
{
    const int*   X   = (const int*)  d_in[0];
    const float* h0  = (const float*)d_in[1];
    const float* c0  = (const float*)d_in[2];
    const float* emb = (const float*)d_in[3];
    const float* Ui  = (const float*)d_in[4];
    const float* Vi  = (const float*)d_in[5];
    const float* bi  = (const float*)d_in[6];
    const float* Uf  = (const float*)d_in[7];
    const float* Vf  = (const float*)d_in[8];
    const float* bf  = (const float*)d_in[9];
    const float* Uc  = (const float*)d_in[10];
    const float* Vc  = (const float*)d_in[11];
    const float* bc  = (const float*)d_in[12];
    const float* Uo  = (const float*)d_in[13];
    const float* Vo  = (const float*)d_in[14];
    const float* bo  = (const float*)d_in[15];
    const float* W   = (const float*)d_in[16];
    const float* b   = (const float*)d_in[17];
    float* out = (float*)d_out;

    cudaFuncSetAttribute(lstm_persistent_kernel,
                         cudaFuncAttributeMaxDynamicSharedMemorySize, SMEM_P_BYTES);

    // 1) pack weights (bf16 interleaved), biases, init state, reset barrier
    pack_kernel<<<(NG * (HIDN / 2) + 255) / 256, 256>>>(Ui, Vi, bi, Uf, Vf, bf,
                                                        Uc, Vc, bc, Uo, Vo, bo, h0, c0);
    pack_emb_kernel<<<(int)(((size_t)NCLS * (EMBD / 2) + 255) / 256), 256>>>(emb);

    // 2) all input-side gate preactivations (bf16 tensor cores, 128x128 tiles)
    input_gemm_kernel<<<dim3(NG / 128, (SEQL * BATCH) / 128), 256>>>(X);

    // 3) all 128 recurrent steps in ONE persistent kernel (V resident, 16 warps)
    lstm_persistent_kernel<<<NCTA, PTHREADS, SMEM_P_BYTES>>>();

    // 4) output projection (tf32): out = h_final @ W^T + b
    out_gemm_kernel<<<dim3(NCLS / BN, BATCH / BM), 128>>>(W, b, out);
}

// round 9
// speedup vs baseline: 1.1021x; 1.1021x over previous
#include <cuda_runtime.h>
#include <cuda_bf16.h>
#include <cstdint>
#include <cmath>

#define HIDN 1024
#define EMBD 1024
#define BATCH 256
#define SEQL 128
#define NCLS 32000
#define NG   4096   /* 4*HIDN, gate-interleaved: n = 4*j + g */

#define BM 128
#define BN 64
#define BK 16
#define AS 20
#define BSS 20
#define GS 68
#define VSTR 516
#define ASTR 36          /* steps A-stage stride (u32) */
#define STG_A (128 * ASTR)

#define NCTA 128
#define PTHREADS 256

// ---------------- device scratch (no allocations allowed) ----------------
static __device__ unsigned g_Ub[NG * (HIDN / 2)];            // 8 MB interleaved U, bf16x2
static __device__ unsigned g_Vb[NG * (HIDN / 2)];            // 8 MB interleaved V, bf16x2
static __device__ unsigned g_Eb[(size_t)NCLS * (EMBD / 2)];  // 64 MB emb, bf16x2
static __device__ float    g_ball[NG];
static __device__ float    g_Zin[(size_t)SEQL * BATCH * NG]; // 512 MB input-side gates
static __device__ float    g_h[2][BATCH * HIDN];             // fp32 h (final proj reads [0])
static __device__ unsigned g_hb[2][BATCH * (HIDN / 2)];      // bf16x2 h ping-pong
static __device__ float    g_c[BATCH * HIDN];
static __device__ unsigned g_bar;                            // grid barrier

// ---------------- helpers ----------------
__device__ __forceinline__ float f2tf32(float x) {
    uint32_t r;
    asm("cvt.rna.tf32.f32 %0, %1;" : "=r"(r) : "f"(x));
    return __uint_as_float(r);
}
__device__ __forceinline__ unsigned pack_bf2(float a, float b) {
    __nv_bfloat162 v = __floats2bfloat162_rn(a, b);
    return *reinterpret_cast<unsigned*>(&v);
}
__device__ __forceinline__ float fsig(float x) {
    return __fdividef(1.f, 1.f + __expf(-x));
}
__device__ __forceinline__ void mma_bf16(float* acc, const unsigned* a, const unsigned* b) {
    asm volatile(
        "mma.sync.aligned.m16n8k16.row.col.f32.bf16.bf16.f32 "
        "{%0,%1,%2,%3}, {%4,%5,%6,%7}, {%8,%9}, {%0,%1,%2,%3};"
        : "+f"(acc[0]), "+f"(acc[1]), "+f"(acc[2]), "+f"(acc[3])
        : "r"(a[0]), "r"(a[1]), "r"(a[2]), "r"(a[3]), "r"(b[0]), "r"(b[1]));
}
__device__ __forceinline__ uint32_t smem_u32(const void* p) {
    uint32_t a;
    asm("{ .reg .u64 t; cvta.to.shared.u64 t, %1; cvt.u32.u64 %0, t; }" : "=r"(a) : "l"(p));
    return a;
}
#define LDSM_X4(r0, r1, r2, r3, addr) \
    asm volatile("ldmatrix.sync.aligned.m8n8.x4.shared.b16 {%0,%1,%2,%3}, [%4];" \
                 : "=r"(r0), "=r"(r1), "=r"(r2), "=r"(r3) : "r"(addr))

// ---------------- pack: interleave U/V (bf16), biases, init state ----------------
__global__ void pack_kernel(const float* __restrict__ Ui, const float* __restrict__ Vi, const float* __restrict__ bi,
                            const float* __restrict__ Uf, const float* __restrict__ Vf, const float* __restrict__ bf,
                            const float* __restrict__ Uc, const float* __restrict__ Vc, const float* __restrict__ bc,
                            const float* __restrict__ Uo, const float* __restrict__ Vo, const float* __restrict__ bo,
                            const float* __restrict__ h0, const float* __restrict__ c0)
{
    int idx = blockIdx.x * blockDim.x + threadIdx.x;
    if (idx >= NG * (HIDN / 2)) return;
    if (idx == 0) g_bar = 0u;
    int n = idx >> 9;
    int k2 = idx & 511;
    int j = n >> 2, g = n & 3;
    const float *U, *V, *bb;
    if (g == 0)      { U = Ui; V = Vi; bb = bi; }
    else if (g == 1) { U = Uf; V = Vf; bb = bf; }
    else if (g == 2) { U = Uc; V = Vc; bb = bc; }
    else             { U = Uo; V = Vo; bb = bo; }
    const float* Up = U + (size_t)j * HIDN + 2 * k2;
    const float* Vp = V + (size_t)j * HIDN + 2 * k2;
    g_Ub[idx] = pack_bf2(Up[0], Up[1]);
    g_Vb[idx] = pack_bf2(Vp[0], Vp[1]);
    if (k2 == 0) g_ball[n] = bb[j];
    if (idx < BATCH * (HIDN / 2)) {
        g_hb[0][idx] = pack_bf2(h0[2 * idx], h0[2 * idx + 1]);
        float2 hv; hv.x = h0[2 * idx]; hv.y = h0[2 * idx + 1];
        *(float2*)&g_h[0][2 * idx] = hv;
        float2 cv; cv.x = c0[2 * idx]; cv.y = c0[2 * idx + 1];
        *(float2*)&g_c[2 * idx] = cv;
    }
}

__global__ void pack_emb_kernel(const float* __restrict__ emb)
{
    size_t idx = (size_t)blockIdx.x * blockDim.x + threadIdx.x;
    if (idx >= (size_t)NCLS * (EMBD / 2)) return;
    g_Eb[idx] = pack_bf2(emb[2 * idx], emb[2 * idx + 1]);
}

// ---------------- bf16 input GEMM: Zin = gather(emb,X) @ Uall^T + ball ----------------
// grid (32, 256), 256 threads, CTA tile 128x128, warp tile 64x32, ldmatrix frag loads
__global__ __launch_bounds__(256, 2)
void input_gemm_kernel(const int* __restrict__ Xids)
{
    const int tid  = threadIdx.x;
    const int lane = tid & 31;
    const int warp = tid >> 5;
    const int wm = (warp >> 2) * 64;
    const int wn = (warp & 3) * 32;
    const int n0 = blockIdx.x * 128;
    const int m0 = blockIdx.y * 128;

    __shared__ unsigned smA[2][128 * 20];
    __shared__ unsigned smB[2][128 * 20];
    __shared__ int vrow[128];

    if (tid < 128) {
        int r = m0 + tid;
        vrow[tid] = Xids[(r & 255) * SEQL + (r >> 8)];
    }
    __syncthreads();

    const uint32_t smA_u = smem_u32(smA);
    const uint32_t smB_u = smem_u32(smB);

    // ldmatrix per-lane offsets (u32 units, relative to buffer base)
    // A frag (m16k16, x4): row = wm + mt*16 + (lane&7) + ((lane>>3)&1)*8 ; col += ((lane>>4)&1)*4
    uint32_t aoff[4];
#pragma unroll
    for (int mt = 0; mt < 4; mt++)
        aoff[mt] = (uint32_t)(wm + mt * 16 + (lane & 7) + ((lane >> 3) & 1) * 8) * 20
                 + ((lane >> 4) & 1) * 4;
    // B pair (2x n8k16, x4): row = wn + p*16 + (lane&7) + ((lane>>4)&1)*8 ; col += ((lane>>3)&1)*4
    uint32_t boff[2];
#pragma unroll
    for (int p = 0; p < 2; p++)
        boff[p] = (uint32_t)(wn + p * 16 + (lane & 7) + ((lane >> 4) & 1) * 8) * 20
                + ((lane >> 3) & 1) * 4;

    const int kcol  = (tid & 3) * 4;
    const int ldrow = tid >> 2;

    const unsigned* ap0 = g_Eb + (size_t)vrow[ldrow] * 512 + kcol;
    const unsigned* ap1 = g_Eb + (size_t)vrow[ldrow + 64] * 512 + kcol;
    const unsigned* bp0 = g_Ub + (size_t)(n0 + ldrow) * 512 + kcol;
    const unsigned* bp1 = g_Ub + (size_t)(n0 + ldrow + 64) * 512 + kcol;

    float acc[4][4][4];
#pragma unroll
    for (int a = 0; a < 4; a++)
#pragma unroll
        for (int b_ = 0; b_ < 4; b_++)
#pragma unroll
            for (int c_ = 0; c_ < 4; c_++) acc[a][b_][c_] = 0.f;

    uint4 a0 = *(const uint4*)ap0;
    uint4 a1 = *(const uint4*)ap1;
    uint4 b0 = *(const uint4*)bp0;
    uint4 b1 = *(const uint4*)bp1;
    *(uint4*)&smA[0][ldrow * 20 + kcol]        = a0;
    *(uint4*)&smA[0][(ldrow + 64) * 20 + kcol] = a1;
    *(uint4*)&smB[0][ldrow * 20 + kcol]        = b0;
    *(uint4*)&smB[0][(ldrow + 64) * 20 + kcol] = b1;
    __syncthreads();

    for (int kc = 0; kc < 32; kc++) {
        const int cur = kc & 1;
        if (kc + 1 < 32) {
            a0 = *(const uint4*)(ap0 + (kc + 1) * 16);
            a1 = *(const uint4*)(ap1 + (kc + 1) * 16);
            b0 = *(const uint4*)(bp0 + (kc + 1) * 16);
            b1 = *(const uint4*)(bp1 + (kc + 1) * 16);
        }
        const uint32_t abase = smA_u + (uint32_t)cur * (128 * 20 * 4);
        const uint32_t bbase = smB_u + (uint32_t)cur * (128 * 20 * 4);
#pragma unroll
        for (int ks = 0; ks < 2; ks++) {
            unsigned af[4][4], bfr[4][2];
#pragma unroll
            for (int mt = 0; mt < 4; mt++)
                LDSM_X4(af[mt][0], af[mt][1], af[mt][2], af[mt][3],
                        abase + (aoff[mt] + ks * 8) * 4);
#pragma unroll
            for (int p = 0; p < 2; p++)
                LDSM_X4(bfr[2 * p][0], bfr[2 * p][1], bfr[2 * p + 1][0], bfr[2 * p + 1][1],
                        bbase + (boff[p] + ks * 8) * 4);
#pragma unroll
            for (int mt = 0; mt < 4; mt++)
#pragma unroll
                for (int nt = 0; nt < 4; nt++)
                    mma_bf16(acc[mt][nt], af[mt], bfr[nt]);
        }
        if (kc + 1 < 32) {
            const int nxt = (kc + 1) & 1;
            *(uint4*)&smA[nxt][ldrow * 20 + kcol]        = a0;
            *(uint4*)&smA[nxt][(ldrow + 64) * 20 + kcol] = a1;
            *(uint4*)&smB[nxt][ldrow * 20 + kcol]        = b0;
            *(uint4*)&smB[nxt][(ldrow + 64) * 20 + kcol] = b1;
        }
        __syncthreads();
    }

#pragma unroll
    for (int mt = 0; mt < 4; mt++) {
#pragma unroll
        for (int nt = 0; nt < 4; nt++) {
            int r = m0 + wm + mt * 16 + (lane >> 2);
            int cidx = n0 + wn + nt * 8 + (lane & 3) * 2;
            float2 bv = *(const float2*)&g_ball[cidx];
            float2 o0; o0.x = acc[mt][nt][0] + bv.x; o0.y = acc[mt][nt][1] + bv.y;
            float2 o1; o1.x = acc[mt][nt][2] + bv.x; o1.y = acc[mt][nt][3] + bv.y;
            *(float2*)&g_Zin[(size_t)r * NG + cidx] = o0;
            *(float2*)&g_Zin[(size_t)(r + 8) * NG + cidx] = o1;
        }
    }
}

// ---------------- persistent recurrent kernel (R7 shape + ldmatrix) ----------------
// 256 threads, 8 warps (2/SMSP), warp tile 32x32, K-chunk 32 half2 (16 iterations)
#define SMEM_P_BYTES ((64 * VSTR) * 4 + 2 * STG_A * 4)

__global__ __launch_bounds__(PTHREADS, 1)
void lstm_persistent_kernel()
{
    extern __shared__ unsigned smem[];
    unsigned* smV = smem;
    unsigned* smA = smem + 64 * VSTR;
    float*    smG = (float*)(smem + 64 * VSTR);

    const int tid  = threadIdx.x;
    const int lane = tid & 31;
    const int warp = tid >> 5;
    const int wm = (warp >> 1) * 32;
    const int wn = (warp & 1) * 32;
    const int bid = blockIdx.x;
    const int m0  = (bid & 1) * 128;
    const int nsl = bid >> 1;
    const int n0  = nsl * 64;

    for (int i = tid; i < 64 * 128; i += PTHREADS) {
        int n = i >> 7, k4 = (i & 127) * 4;
        *(uint4*)&smV[n * VSTR + k4] = *(const uint4*)&g_Vb[(size_t)(n0 + n) * 512 + k4];
    }

    float creg[4][2];
#pragma unroll
    for (int it = 0; it < 4; it++) {
        int idx = tid + it * PTHREADS;
        int lr = idx >> 3, jp = idx & 7;
        float2 cv = *(const float2*)&g_c[(m0 + lr) * HIDN + nsl * 16 + jp * 2];
        creg[it][0] = cv.x; creg[it][1] = cv.y;
    }

    const uint32_t smA_u = smem_u32(smA);
    const uint32_t smV_u = smem_u32(smV);

    // ldmatrix per-lane offsets (u32 units)
    uint32_t aoff[2];
#pragma unroll
    for (int mt = 0; mt < 2; mt++)
        aoff[mt] = (uint32_t)(wm + mt * 16 + (lane & 7) + ((lane >> 3) & 1) * 8) * ASTR
                 + ((lane >> 4) & 1) * 4;
    uint32_t voff[2];
#pragma unroll
    for (int p = 0; p < 2; p++)
        voff[p] = (uint32_t)(wn + p * 16 + (lane & 7) + ((lane >> 4) & 1) * 8) * VSTR
                + ((lane >> 3) & 1) * 4;

    const int kcol  = (tid & 3) * 4;
    const int ldrow = tid >> 2;
    __syncthreads();

    for (int t = 0; t < SEQL; t++) {
        // prefetch this step's Zin slice early (hidden behind the GEMM)
        float4 zpre[4][2];
#pragma unroll
        for (int it = 0; it < 4; it++) {
            int idx = tid + it * PTHREADS;
            int lr = idx >> 3, jp = idx & 7;
            size_t zb = ((size_t)t * BATCH + m0 + lr) * NG + n0 + jp * 8;
            zpre[it][0] = *(const float4*)&g_Zin[zb];
            zpre[it][1] = *(const float4*)&g_Zin[zb + 4];
        }

        const unsigned* hin = g_hb[t & 1];
        const unsigned* arp0 = hin + (size_t)(m0 + ldrow) * 512 + kcol;
        const unsigned* arp1 = hin + (size_t)(m0 + ldrow + 64) * 512 + kcol;

        float acc[2][4][4];
#pragma unroll
        for (int a = 0; a < 2; a++)
#pragma unroll
            for (int b_ = 0; b_ < 4; b_++)
#pragma unroll
                for (int c_ = 0; c_ < 4; c_++) acc[a][b_][c_] = 0.f;

        // K-chunk = 32 half2 (64 bf16), 16 iterations
        uint4 a00 = *(const uint4*)arp0;
        uint4 a01 = *(const uint4*)(arp0 + 16);
        uint4 a10 = *(const uint4*)arp1;
        uint4 a11 = *(const uint4*)(arp1 + 16);
        *(uint4*)&smA[ldrow * ASTR + kcol]             = a00;
        *(uint4*)&smA[ldrow * ASTR + kcol + 16]        = a01;
        *(uint4*)&smA[(ldrow + 64) * ASTR + kcol]      = a10;
        *(uint4*)&smA[(ldrow + 64) * ASTR + kcol + 16] = a11;
        __syncthreads();

        for (int kc = 0; kc < 16; kc++) {
            const int cur = kc & 1;
            if (kc + 1 < 16) {
                a00 = *(const uint4*)(arp0 + (kc + 1) * 32);
                a01 = *(const uint4*)(arp0 + (kc + 1) * 32 + 16);
                a10 = *(const uint4*)(arp1 + (kc + 1) * 32);
                a11 = *(const uint4*)(arp1 + (kc + 1) * 32 + 16);
            }
            const uint32_t abase = smA_u + (uint32_t)cur * (STG_A * 4);
            const uint32_t vbase = smV_u + (uint32_t)(kc * 32) * 4;
#pragma unroll
            for (int ks = 0; ks < 4; ks++) {
                unsigned af[2][4], bfr[4][2];
#pragma unroll
                for (int mtw = 0; mtw < 2; mtw++)
                    LDSM_X4(af[mtw][0], af[mtw][1], af[mtw][2], af[mtw][3],
                            abase + (aoff[mtw] + ks * 8) * 4);
#pragma unroll
                for (int p = 0; p < 2; p++)
                    LDSM_X4(bfr[2 * p][0], bfr[2 * p][1], bfr[2 * p + 1][0], bfr[2 * p + 1][1],
                            vbase + (voff[p] + ks * 8) * 4);
#pragma unroll
                for (int mtw = 0; mtw < 2; mtw++)
#pragma unroll
                    for (int ntw = 0; ntw < 4; ntw++)
                        mma_bf16(acc[mtw][ntw], af[mtw], bfr[ntw]);
            }
            if (kc + 1 < 16) {
                unsigned* Ad = smA + ((kc + 1) & 1) * STG_A;
                *(uint4*)&Ad[ldrow * ASTR + kcol]             = a00;
                *(uint4*)&Ad[ldrow * ASTR + kcol + 16]        = a01;
                *(uint4*)&Ad[(ldrow + 64) * ASTR + kcol]      = a10;
                *(uint4*)&Ad[(ldrow + 64) * ASTR + kcol + 16] = a11;
            }
            __syncthreads();
        }

        // accum -> smem gate tile (overlays A staging; all mma reads done)
#pragma unroll
        for (int mtw = 0; mtw < 2; mtw++)
#pragma unroll
            for (int ntw = 0; ntw < 4; ntw++) {
                int lr = wm + mtw * 16 + (lane >> 2);
                int lc = wn + ntw * 8 + (lane & 3) * 2;
                smG[lr * GS + lc]           = acc[mtw][ntw][0];
                smG[lr * GS + lc + 1]       = acc[mtw][ntw][1];
                smG[(lr + 8) * GS + lc]     = acc[mtw][ntw][2];
                smG[(lr + 8) * GS + lc + 1] = acc[mtw][ntw][3];
            }
        __syncthreads();

        // fused LSTM cell (c in registers)
        unsigned* hbout = g_hb[(t & 1) ^ 1];
#pragma unroll
        for (int it = 0; it < 4; it++) {
            int idx = tid + it * PTHREADS;
            int lr = idx >> 3, jp = idx & 7;
            int m = m0 + lr;
            float4 z0 = zpre[it][0];
            float4 z1 = zpre[it][1];
            const float* Gp = &smG[lr * GS + jp * 8];

            float i0 = fsig(Gp[0] + z0.x);
            float f0 = fsig(Gp[1] + z0.y);
            float g0 = tanhf(Gp[2] + z0.z);
            float o0 = fsig(Gp[3] + z0.w);
            float i1 = fsig(Gp[4] + z1.x);
            float f1 = fsig(Gp[5] + z1.y);
            float g1 = tanhf(Gp[6] + z1.z);
            float o1 = fsig(Gp[7] + z1.w);

            float cn0 = f0 * creg[it][0] + i0 * g0;
            float cn1 = f1 * creg[it][1] + i1 * g1;
            creg[it][0] = cn0; creg[it][1] = cn1;

            float h0v = o0 * tanhf(cn0);
            float h1v = o1 * tanhf(cn1);
            hbout[m * 512 + nsl * 8 + jp] = pack_bf2(h0v, h1v);
            if (t == SEQL - 1) {
                float2 hf; hf.x = h0v; hf.y = h1v;
                *(float2*)&g_h[0][m * HIDN + nsl * 16 + jp * 2] = hf;
            }
        }

        if (t < SEQL - 1) {
            __syncthreads();
            if (tid == 0) {
                __threadfence();
                atomicAdd(&g_bar, 1u);
                const unsigned target = (unsigned)NCTA * (t + 1);
                unsigned v;
                do {
                    asm volatile("ld.acquire.gpu.u32 %0, [%1];"
                                 : "=r"(v) : "l"(&g_bar) : "memory");
                } while (v < target);
            }
            __syncthreads();
        }
    }
}

// ---------------- tf32 output projection: out = h_final @ W^T + b ----------------
__global__ __launch_bounds__(128)
void out_gemm_kernel(const float* __restrict__ W,
                     const float* __restrict__ biasp,
                     float* __restrict__ Cout)
{
    const int tid  = threadIdx.x;
    const int lane = tid & 31;
    const int warp = tid >> 5;
    const int wm = (warp >> 1) * 64;
    const int wn = (warp & 1) * 32;
    const int n0 = blockIdx.x * BN;
    const int m0 = blockIdx.y * BM;

    __shared__ struct { float A[2][BM * AS]; float B[2][BN * BSS]; } sm;

    const float* Ain = g_h[0];
    const int kcol  = (tid & 3) * 4;
    const int ldrow = tid >> 2;

    const float* arp[4];
#pragma unroll
    for (int i = 0; i < 4; i++)
        arp[i] = Ain + (size_t)(m0 + ldrow + 32 * i) * HIDN + kcol;
    const float* brp[2];
#pragma unroll
    for (int i = 0; i < 2; i++)
        brp[i] = W + (size_t)(n0 + ldrow + 32 * i) * HIDN + kcol;

    float4 areg[4], breg[2];
    float acc[4][4][4];
#pragma unroll
    for (int a = 0; a < 4; a++)
#pragma unroll
        for (int b_ = 0; b_ < 4; b_++)
#pragma unroll
            for (int c_ = 0; c_ < 4; c_++) acc[a][b_][c_] = 0.f;

#pragma unroll
    for (int i = 0; i < 4; i++) areg[i] = *(const float4*)(arp[i]);
#pragma unroll
    for (int i = 0; i < 2; i++) breg[i] = *(const float4*)(brp[i]);
#pragma unroll
    for (int i = 0; i < 4; i++) {
        float4 v = areg[i];
        v.x = f2tf32(v.x); v.y = f2tf32(v.y); v.z = f2tf32(v.z); v.w = f2tf32(v.w);
        *(float4*)&sm.A[0][(ldrow + 32 * i) * AS + kcol] = v;
    }
#pragma unroll
    for (int i = 0; i < 2; i++) {
        float4 v = breg[i];
        v.x = f2tf32(v.x); v.y = f2tf32(v.y); v.z = f2tf32(v.z); v.w = f2tf32(v.w);
        *(float4*)&sm.B[0][(ldrow + 32 * i) * BSS + kcol] = v;
    }
    __syncthreads();

    const int NCH = HIDN / BK;
    for (int kc = 0; kc < NCH; kc++) {
        int cur = kc & 1;
        if (kc + 1 < NCH) {
#pragma unroll
            for (int i = 0; i < 4; i++) areg[i] = *(const float4*)(arp[i] + (kc + 1) * BK);
#pragma unroll
            for (int i = 0; i < 2; i++) breg[i] = *(const float4*)(brp[i] + (kc + 1) * BK);
        }
#pragma unroll
        for (int k8 = 0; k8 < BK; k8 += 8) {
            uint32_t af[4][4], bfr[4][2];
#pragma unroll
            for (int mt = 0; mt < 4; mt++) {
                const float* ap = &sm.A[cur][(wm + mt * 16 + (lane >> 2)) * AS + k8 + (lane & 3)];
                af[mt][0] = __float_as_uint(ap[0]);
                af[mt][1] = __float_as_uint(ap[8 * AS]);
                af[mt][2] = __float_as_uint(ap[4]);
                af[mt][3] = __float_as_uint(ap[8 * AS + 4]);
            }
#pragma unroll
            for (int nt = 0; nt < 4; nt++) {
                const float* bp = &sm.B[cur][(wn + nt * 8 + (lane >> 2)) * BSS + k8 + (lane & 3)];
                bfr[nt][0] = __float_as_uint(bp[0]);
                bfr[nt][1] = __float_as_uint(bp[4]);
            }
#pragma unroll
            for (int mt = 0; mt < 4; mt++)
#pragma unroll
                for (int nt = 0; nt < 4; nt++)
                    asm volatile(
                        "mma.sync.aligned.m16n8k8.row.col.f32.tf32.tf32.f32 "
                        "{%0,%1,%2,%3}, {%4,%5,%6,%7}, {%8,%9}, {%0,%1,%2,%3};"
                        : "+f"(acc[mt][nt][0]), "+f"(acc[mt][nt][1]),
                          "+f"(acc[mt][nt][2]), "+f"(acc[mt][nt][3])
                        : "r"(af[mt][0]), "r"(af[mt][1]), "r"(af[mt][2]), "r"(af[mt][3]),
                          "r"(bfr[nt][0]), "r"(bfr[nt][1]));
        }
        if (kc + 1 < NCH) {
            int nxt = cur ^ 1;
#pragma unroll
            for (int i = 0; i < 4; i++) {
                float4 v = areg[i];
                v.x = f2tf32(v.x); v.y = f2tf32(v.y); v.z = f2tf32(v.z); v.w = f2tf32(v.w);
                *(float4*)&sm.A[nxt][(ldrow + 32 * i) * AS + kcol] = v;
            }
#pragma unroll
            for (int i = 0; i < 2; i++) {
                float4 v = breg[i];
                v.x = f2tf32(v.x); v.y = f2tf32(v.y); v.z = f2tf32(v.z); v.w = f2tf32(v.w);
                *(float4*)&sm.B[nxt][(ldrow + 32 * i) * BSS + kcol] = v;
            }
        }
        __syncthreads();
    }

#pragma unroll
    for (int mt = 0; mt < 4; mt++) {
#pragma unroll
        for (int nt = 0; nt < 4; nt++) {
            int r = m0 + wm + mt * 16 + (lane >> 2);
            int cidx = n0 + wn + nt * 8 + (lane & 3) * 2;
            float2 bv = *(const float2*)&biasp[cidx];
            float2 v0; v0.x = acc[mt][nt][0] + bv.x; v0.y = acc[mt][nt][1] + bv.y;
            float2 v1; v1.x = acc[mt][nt][2] + bv.x; v1.y = acc[mt][nt][3] + bv.y;
            *(float2*)&Cout[(size_t)r * NCLS + cidx] = v0;
            *(float2*)&Cout[(size_t)(r + 8) * NCLS + cidx] = v1;
        }
    }
}

// ---------------- launch ----------------
extern "C" void kernel_launch(void* const* d_in, const int* in_sizes, int n_in,
                              void* d_out, int out_size)
{
    const int*   X   = (const int*)  d_in[0];
    const float* h0  = (const float*)d_in[1];
    const float* c0  = (const float*)d_in[2];
    const float* emb = (const float*)d_in[3];
    const float* Ui  = (const float*)d_in[4];
    const float* Vi  = (const float*)d_in[5];
    const float* bi  = (const float*)d_in[6];
    const float* Uf  = (const float*)d_in[7];
    const float* Vf  = (const float*)d_in[8];
    const float* bf  = (const float*)d_in[9];
    const float* Uc  = (const float*)d_in[10];
    const float* Vc  = (const float*)d_in[11];
    const float* bc  = (const float*)d_in[12];
    const float* Uo  = (const float*)d_in[13];
    const float* Vo  = (const float*)d_in[14];
    const float* bo  = (const float*)d_in[15];
    const float* W   = (const float*)d_in[16];
    const float* b   = (const float*)d_in[17];
    float* out = (float*)d_out;

    cudaFuncSetAttribute(lstm_persistent_kernel,
                         cudaFuncAttributeMaxDynamicSharedMemorySize, SMEM_P_BYTES);

    // 1) pack weights (bf16 interleaved), biases, init state, reset barrier
    pack_kernel<<<(NG * (HIDN / 2) + 255) / 256, 256>>>(Ui, Vi, bi, Uf, Vf, bf,
                                                        Uc, Vc, bc, Uo, Vo, bo, h0, c0);
    pack_emb_kernel<<<(int)(((size_t)NCLS * (EMBD / 2) + 255) / 256), 256>>>(emb);

    // 2) all input-side gate preactivations (bf16 tensor cores, ldmatrix)
    input_gemm_kernel<<<dim3(NG / 128, (SEQL * BATCH) / 128), 256>>>(X);

    // 3) all 128 recurrent steps in ONE persistent kernel (V resident, ldmatrix)
    lstm_persistent_kernel<<<NCTA, PTHREADS, SMEM_P_BYTES>>>();

    // 4) output projection (tf32): out = h_final @ W^T + b
    out_gemm_kernel<<<dim3(NCLS / BN, BATCH / BM), 128>>>(W, b, out);
}

// round 10
// speedup vs baseline: 1.1861x; 1.0762x over previous
#include <cuda_runtime.h>
#include <cuda_bf16.h>
#include <cstdint>
#include <cmath>

#define HIDN 1024
#define EMBD 1024
#define BATCH 256
#define SEQL 128
#define NCLS 32000
#define NG   4096   /* 4*HIDN, gate-interleaved: n = 4*j + g */

#define BM 128
#define BN 64
#define BK 16
#define AS 20
#define BSS 20
#define GS 68
#define VSTR 516
#define ASTR 36          /* stage stride (u32), conflict-free for ldmatrix */
#define STG_A (128 * ASTR)

#define NCTA 128
#define PTHREADS 256

// input-GEMM cp.async pipeline geometry
#define IG_STAGE_U32 (2 * 128 * ASTR)   /* A(128x36) + B(128x36) u32 per stage = 9216 */
#define IG_STAGE_B   (IG_STAGE_U32 * 4) /* 36864 B */
#define IG_BOFF_B    (128 * ASTR * 4)   /* B region offset within stage = 18432 B */
#define IG_SMEM_B    (3 * IG_STAGE_B)   /* 110592 B */

// ---------------- device scratch (no allocations allowed) ----------------
static __device__ unsigned g_Ub[NG * (HIDN / 2)];            // 8 MB interleaved U, bf16x2
static __device__ unsigned g_Vb[NG * (HIDN / 2)];            // 8 MB interleaved V, bf16x2
static __device__ unsigned g_Eb[(size_t)NCLS * (EMBD / 2)];  // 64 MB emb, bf16x2
static __device__ float    g_ball[NG];
static __device__ float    g_Zin[(size_t)SEQL * BATCH * NG]; // 512 MB input-side gates
static __device__ float    g_h[2][BATCH * HIDN];             // fp32 h (final proj reads [0])
static __device__ unsigned g_hb[2][BATCH * (HIDN / 2)];      // bf16x2 h ping-pong
static __device__ float    g_c[BATCH * HIDN];
static __device__ unsigned g_barA[32];                       // 2 barrier counters (slots 0,16)

// ---------------- helpers ----------------
__device__ __forceinline__ float f2tf32(float x) {
    uint32_t r;
    asm("cvt.rna.tf32.f32 %0, %1;" : "=r"(r) : "f"(x));
    return __uint_as_float(r);
}
__device__ __forceinline__ unsigned pack_bf2(float a, float b) {
    __nv_bfloat162 v = __floats2bfloat162_rn(a, b);
    return *reinterpret_cast<unsigned*>(&v);
}
__device__ __forceinline__ float fsig(float x) {
    return __fdividef(1.f, 1.f + __expf(-x));
}
__device__ __forceinline__ void mma_bf16(float* acc, const unsigned* a, const unsigned* b) {
    asm volatile(
        "mma.sync.aligned.m16n8k16.row.col.f32.bf16.bf16.f32 "
        "{%0,%1,%2,%3}, {%4,%5,%6,%7}, {%8,%9}, {%0,%1,%2,%3};"
        : "+f"(acc[0]), "+f"(acc[1]), "+f"(acc[2]), "+f"(acc[3])
        : "r"(a[0]), "r"(a[1]), "r"(a[2]), "r"(a[3]), "r"(b[0]), "r"(b[1]));
}
__device__ __forceinline__ uint32_t smem_u32(const void* p) {
    uint32_t a;
    asm("{ .reg .u64 t; cvta.to.shared.u64 t, %1; cvt.u32.u64 %0, t; }" : "=r"(a) : "l"(p));
    return a;
}
#define LDSM_X4(r0, r1, r2, r3, addr) \
    asm volatile("ldmatrix.sync.aligned.m8n8.x4.shared.b16 {%0,%1,%2,%3}, [%4];" \
                 : "=r"(r0), "=r"(r1), "=r"(r2), "=r"(r3) : "r"(addr))
#define CP_ASYNC16(dst, src) \
    asm volatile("cp.async.cg.shared.global [%0], [%1], 16;" :: "r"(dst), "l"(src))
#define CP_COMMIT() asm volatile("cp.async.commit_group;" ::: "memory")
#define CP_WAIT1()  asm volatile("cp.async.wait_group 1;" ::: "memory")

// ---------------- pack: interleave U/V (bf16), biases, init state ----------------
__global__ void pack_kernel(const float* __restrict__ Ui, const float* __restrict__ Vi, const float* __restrict__ bi,
                            const float* __restrict__ Uf, const float* __restrict__ Vf, const float* __restrict__ bf,
                            const float* __restrict__ Uc, const float* __restrict__ Vc, const float* __restrict__ bc,
                            const float* __restrict__ Uo, const float* __restrict__ Vo, const float* __restrict__ bo,
                            const float* __restrict__ h0, const float* __restrict__ c0)
{
    int idx = blockIdx.x * blockDim.x + threadIdx.x;
    if (idx >= NG * (HIDN / 2)) return;
    if (idx < 32) g_barA[idx] = 0u;
    int n = idx >> 9;
    int k2 = idx & 511;
    int j = n >> 2, g = n & 3;
    const float *U, *V, *bb;
    if (g == 0)      { U = Ui; V = Vi; bb = bi; }
    else if (g == 1) { U = Uf; V = Vf; bb = bf; }
    else if (g == 2) { U = Uc; V = Vc; bb = bc; }
    else             { U = Uo; V = Vo; bb = bo; }
    const float* Up = U + (size_t)j * HIDN + 2 * k2;
    const float* Vp = V + (size_t)j * HIDN + 2 * k2;
    g_Ub[idx] = pack_bf2(Up[0], Up[1]);
    g_Vb[idx] = pack_bf2(Vp[0], Vp[1]);
    if (k2 == 0) g_ball[n] = bb[j];
    if (idx < BATCH * (HIDN / 2)) {
        g_hb[0][idx] = pack_bf2(h0[2 * idx], h0[2 * idx + 1]);
        float2 hv; hv.x = h0[2 * idx]; hv.y = h0[2 * idx + 1];
        *(float2*)&g_h[0][2 * idx] = hv;
        float2 cv; cv.x = c0[2 * idx]; cv.y = c0[2 * idx + 1];
        *(float2*)&g_c[2 * idx] = cv;
    }
}

__global__ void pack_emb_kernel(const float* __restrict__ emb)
{
    size_t idx = (size_t)blockIdx.x * blockDim.x + threadIdx.x;
    if (idx >= (size_t)NCLS * (EMBD / 2)) return;
    g_Eb[idx] = pack_bf2(emb[2 * idx], emb[2 * idx + 1]);
}

// ---------------- bf16 input GEMM: Zin = gather(emb,X) @ Uall^T + ball ----------------
// grid (32, 256), 256 threads, CTA tile 128x128, warp tile 64x32.
// cp.async 3-stage pipeline, K-chunk 32 half2 (16 chunks, 1 sync/chunk), ldmatrix frags.
__global__ __launch_bounds__(256, 2)
void input_gemm_kernel(const int* __restrict__ Xids)
{
    extern __shared__ unsigned igsm[];
    __shared__ int vrow[128];

    const int tid  = threadIdx.x;
    const int lane = tid & 31;
    const int warp = tid >> 5;
    const int wm = (warp >> 2) * 64;
    const int wn = (warp & 3) * 32;
    const int n0 = blockIdx.x * 128;
    const int m0 = blockIdx.y * 128;

    if (tid < 128) {
        int r = m0 + tid;
        vrow[tid] = Xids[(r & 255) * SEQL + (r >> 8)];
    }
    __syncthreads();

    const uint32_t sbase = smem_u32(igsm);

    // per-thread cp.async assignments: 4 A rows-chunks + 4 B rows-chunks
    // idx = tid + i*256 (0..1023): row = idx>>3 (0..127), 16B-block cb = idx&7
    const unsigned* srcA[4];
    const unsigned* srcB[4];
    uint32_t dstoff[4];   // (row*ASTR + cb*4)*4, shared by A and B regions
#pragma unroll
    for (int i = 0; i < 4; i++) {
        int idx = tid + i * 256;
        int row = idx >> 3, cb = idx & 7;
        srcA[i] = g_Eb + (size_t)vrow[row] * 512 + cb * 4;
        srcB[i] = g_Ub + (size_t)(n0 + row) * 512 + cb * 4;
        dstoff[i] = (uint32_t)(row * ASTR + cb * 4) * 4;
    }

    // ldmatrix per-lane offsets (u32 units, relative to region base)
    uint32_t aoff[4];
#pragma unroll
    for (int mt = 0; mt < 4; mt++)
        aoff[mt] = (uint32_t)(wm + mt * 16 + (lane & 7) + ((lane >> 3) & 1) * 8) * ASTR
                 + ((lane >> 4) & 1) * 4;
    uint32_t boff[2];
#pragma unroll
    for (int p = 0; p < 2; p++)
        boff[p] = (uint32_t)(wn + p * 16 + (lane & 7) + ((lane >> 4) & 1) * 8) * ASTR
                + ((lane >> 3) & 1) * 4;

    float acc[4][4][4];
#pragma unroll
    for (int a = 0; a < 4; a++)
#pragma unroll
        for (int b_ = 0; b_ < 4; b_++)
#pragma unroll
            for (int c_ = 0; c_ < 4; c_++) acc[a][b_][c_] = 0.f;

    // issue stage s (chunk s): 32 half2 per row = 128B -> 8 x 16B per row
    auto issue = [&](int chunk, int stage) {
        uint32_t base = sbase + (uint32_t)stage * IG_STAGE_B;
#pragma unroll
        for (int i = 0; i < 4; i++) {
            CP_ASYNC16(base + dstoff[i], srcA[i] + chunk * 32);
            CP_ASYNC16(base + IG_BOFF_B + dstoff[i], srcB[i] + chunk * 32);
        }
        CP_COMMIT();
    };

    issue(0, 0);
    issue(1, 1);

    int cur = 0, nxt = 2;
    for (int kc = 0; kc < 16; kc++) {
        CP_WAIT1();          // chunk kc landed
        __syncthreads();     // visible CTA-wide; also guards buffer reuse

        const uint32_t abase = sbase + (uint32_t)cur * IG_STAGE_B;
        const uint32_t bbase = abase + IG_BOFF_B;
#pragma unroll
        for (int ks = 0; ks < 4; ks++) {
            unsigned af[4][4], bfr[4][2];
#pragma unroll
            for (int mt = 0; mt < 4; mt++)
                LDSM_X4(af[mt][0], af[mt][1], af[mt][2], af[mt][3],
                        abase + (aoff[mt] + ks * 8) * 4);
#pragma unroll
            for (int p = 0; p < 2; p++)
                LDSM_X4(bfr[2 * p][0], bfr[2 * p][1], bfr[2 * p + 1][0], bfr[2 * p + 1][1],
                        bbase + (boff[p] + ks * 8) * 4);
#pragma unroll
            for (int mt = 0; mt < 4; mt++)
#pragma unroll
                for (int nt = 0; nt < 4; nt++)
                    mma_bf16(acc[mt][nt], af[mt], bfr[nt]);
        }
        if (kc + 2 < 16) issue(kc + 2, nxt);
        else CP_COMMIT();    // keep group count in lockstep for CP_WAIT1 semantics
        cur = (cur == 2) ? 0 : cur + 1;
        nxt = (nxt == 2) ? 0 : nxt + 1;
    }

    // epilogue: + bias, store fp32 Zin (row-major [r][n])
#pragma unroll
    for (int mt = 0; mt < 4; mt++) {
#pragma unroll
        for (int nt = 0; nt < 4; nt++) {
            int r = m0 + wm + mt * 16 + (lane >> 2);
            int cidx = n0 + wn + nt * 8 + (lane & 3) * 2;
            float2 bv = *(const float2*)&g_ball[cidx];
            float2 o0; o0.x = acc[mt][nt][0] + bv.x; o0.y = acc[mt][nt][1] + bv.y;
            float2 o1; o1.x = acc[mt][nt][2] + bv.x; o1.y = acc[mt][nt][3] + bv.y;
            *(float2*)&g_Zin[(size_t)r * NG + cidx] = o0;
            *(float2*)&g_Zin[(size_t)(r + 8) * NG + cidx] = o1;
        }
    }
}

// ---------------- persistent recurrent kernel (R9 + split barrier + z-prefetch) ----------------
#define SMEM_P_BYTES ((64 * VSTR) * 4 + 2 * STG_A * 4)

__global__ __launch_bounds__(PTHREADS, 1)
void lstm_persistent_kernel()
{
    extern __shared__ unsigned smem[];
    unsigned* smV = smem;
    unsigned* smA = smem + 64 * VSTR;
    float*    smG = (float*)(smem + 64 * VSTR);

    const int tid  = threadIdx.x;
    const int lane = tid & 31;
    const int warp = tid >> 5;
    const int wm = (warp >> 1) * 32;
    const int wn = (warp & 1) * 32;
    const int bid = blockIdx.x;
    const int m0  = (bid & 1) * 128;
    const int nsl = bid >> 1;
    const int n0  = nsl * 64;
    unsigned* bar = &g_barA[(bid & 1) * 16];   // independent barrier per m-half

    for (int i = tid; i < 64 * 128; i += PTHREADS) {
        int n = i >> 7, k4 = (i & 127) * 4;
        *(uint4*)&smV[n * VSTR + k4] = *(const uint4*)&g_Vb[(size_t)(n0 + n) * 512 + k4];
    }

    float creg[4][2];
#pragma unroll
    for (int it = 0; it < 4; it++) {
        int idx = tid + it * PTHREADS;
        int lr = idx >> 3, jp = idx & 7;
        float2 cv = *(const float2*)&g_c[(m0 + lr) * HIDN + nsl * 16 + jp * 2];
        creg[it][0] = cv.x; creg[it][1] = cv.y;
    }

    const uint32_t smA_u = smem_u32(smA);
    const uint32_t smV_u = smem_u32(smV);

    uint32_t aoff[2];
#pragma unroll
    for (int mt = 0; mt < 2; mt++)
        aoff[mt] = (uint32_t)(wm + mt * 16 + (lane & 7) + ((lane >> 3) & 1) * 8) * ASTR
                 + ((lane >> 4) & 1) * 4;
    uint32_t voff[2];
#pragma unroll
    for (int p = 0; p < 2; p++)
        voff[p] = (uint32_t)(wn + p * 16 + (lane & 7) + ((lane >> 4) & 1) * 8) * VSTR
                + ((lane >> 3) & 1) * 4;

    const int kcol  = (tid & 3) * 4;
    const int ldrow = tid >> 2;

    // Zin prefetch thread mapping (it-invariant jp)
    const int zlr0 = tid >> 3, zjp = tid & 7;
    size_t zrowstride = (size_t)32 * NG;   // +32 batch rows per it step

    // prefetch Zin for step 0
    float4 zpre[4][2];
#pragma unroll
    for (int it = 0; it < 4; it++) {
        size_t zb = ((size_t)0 * BATCH + m0 + zlr0 + it * 32) * NG + n0 + zjp * 8;
        zpre[it][0] = *(const float4*)&g_Zin[zb];
        zpre[it][1] = *(const float4*)&g_Zin[zb + 4];
    }
    __syncthreads();

    for (int t = 0; t < SEQL; t++) {
        const unsigned* hin = g_hb[t & 1];
        const unsigned* arp0 = hin + (size_t)(m0 + ldrow) * 512 + kcol;
        const unsigned* arp1 = hin + (size_t)(m0 + ldrow + 64) * 512 + kcol;

        float acc[2][4][4];
#pragma unroll
        for (int a = 0; a < 2; a++)
#pragma unroll
            for (int b_ = 0; b_ < 4; b_++)
#pragma unroll
                for (int c_ = 0; c_ < 4; c_++) acc[a][b_][c_] = 0.f;

        uint4 a00 = *(const uint4*)arp0;
        uint4 a01 = *(const uint4*)(arp0 + 16);
        uint4 a10 = *(const uint4*)arp1;
        uint4 a11 = *(const uint4*)(arp1 + 16);
        *(uint4*)&smA[ldrow * ASTR + kcol]             = a00;
        *(uint4*)&smA[ldrow * ASTR + kcol + 16]        = a01;
        *(uint4*)&smA[(ldrow + 64) * ASTR + kcol]      = a10;
        *(uint4*)&smA[(ldrow + 64) * ASTR + kcol + 16] = a11;
        __syncthreads();

        for (int kc = 0; kc < 16; kc++) {
            const int cur = kc & 1;
            if (kc + 1 < 16) {
                a00 = *(const uint4*)(arp0 + (kc + 1) * 32);
                a01 = *(const uint4*)(arp0 + (kc + 1) * 32 + 16);
                a10 = *(const uint4*)(arp1 + (kc + 1) * 32);
                a11 = *(const uint4*)(arp1 + (kc + 1) * 32 + 16);
            }
            const uint32_t abase = smA_u + (uint32_t)cur * (STG_A * 4);
            const uint32_t vbase = smV_u + (uint32_t)(kc * 32) * 4;
#pragma unroll
            for (int ks = 0; ks < 4; ks++) {
                unsigned af[2][4], bfr[4][2];
#pragma unroll
                for (int mtw = 0; mtw < 2; mtw++)
                    LDSM_X4(af[mtw][0], af[mtw][1], af[mtw][2], af[mtw][3],
                            abase + (aoff[mtw] + ks * 8) * 4);
#pragma unroll
                for (int p = 0; p < 2; p++)
                    LDSM_X4(bfr[2 * p][0], bfr[2 * p][1], bfr[2 * p + 1][0], bfr[2 * p + 1][1],
                            vbase + (voff[p] + ks * 8) * 4);
#pragma unroll
                for (int mtw = 0; mtw < 2; mtw++)
#pragma unroll
                    for (int ntw = 0; ntw < 4; ntw++)
                        mma_bf16(acc[mtw][ntw], af[mtw], bfr[ntw]);
            }
            if (kc + 1 < 16) {
                unsigned* Ad = smA + ((kc + 1) & 1) * STG_A;
                *(uint4*)&Ad[ldrow * ASTR + kcol]             = a00;
                *(uint4*)&Ad[ldrow * ASTR + kcol + 16]        = a01;
                *(uint4*)&Ad[(ldrow + 64) * ASTR + kcol]      = a10;
                *(uint4*)&Ad[(ldrow + 64) * ASTR + kcol + 16] = a11;
            }
            __syncthreads();
        }

        // accum -> smem gate tile (overlays A staging; all mma reads done)
#pragma unroll
        for (int mtw = 0; mtw < 2; mtw++)
#pragma unroll
            for (int ntw = 0; ntw < 4; ntw++) {
                int lr = wm + mtw * 16 + (lane >> 2);
                int lc = wn + ntw * 8 + (lane & 3) * 2;
                smG[lr * GS + lc]           = acc[mtw][ntw][0];
                smG[lr * GS + lc + 1]       = acc[mtw][ntw][1];
                smG[(lr + 8) * GS + lc]     = acc[mtw][ntw][2];
                smG[(lr + 8) * GS + lc + 1] = acc[mtw][ntw][3];
            }
        __syncthreads();

        // fused LSTM cell (c in registers)
        unsigned* hbout = g_hb[(t & 1) ^ 1];
#pragma unroll
        for (int it = 0; it < 4; it++) {
            int lr = zlr0 + it * 32;
            int m = m0 + lr;
            float4 z0 = zpre[it][0];
            float4 z1 = zpre[it][1];
            const float* Gp = &smG[lr * GS + zjp * 8];

            float i0 = fsig(Gp[0] + z0.x);
            float f0 = fsig(Gp[1] + z0.y);
            float g0 = tanhf(Gp[2] + z0.z);
            float o0 = fsig(Gp[3] + z0.w);
            float i1 = fsig(Gp[4] + z1.x);
            float f1 = fsig(Gp[5] + z1.y);
            float g1 = tanhf(Gp[6] + z1.z);
            float o1 = fsig(Gp[7] + z1.w);

            float cn0 = f0 * creg[it][0] + i0 * g0;
            float cn1 = f1 * creg[it][1] + i1 * g1;
            creg[it][0] = cn0; creg[it][1] = cn1;

            float h0v = o0 * tanhf(cn0);
            float h1v = o1 * tanhf(cn1);
            hbout[m * 512 + nsl * 8 + zjp] = pack_bf2(h0v, h1v);
            if (t == SEQL - 1) {
                float2 hf; hf.x = h0v; hf.y = h1v;
                *(float2*)&g_h[0][m * HIDN + nsl * 16 + zjp * 2] = hf;
            }
        }

        if (t < SEQL - 1) {
            // prefetch next step's Zin BEFORE the barrier (static data; hides DRAM latency
            // behind the barrier spin)
#pragma unroll
            for (int it = 0; it < 4; it++) {
                size_t zb = ((size_t)(t + 1) * BATCH + m0 + zlr0 + it * 32) * NG + n0 + zjp * 8;
                zpre[it][0] = *(const float4*)&g_Zin[zb];
                zpre[it][1] = *(const float4*)&g_Zin[zb + 4];
            }
            __syncthreads();
            if (tid == 0) {
                __threadfence();
                atomicAdd(bar, 1u);
                const unsigned target = 64u * (t + 1);
                unsigned v;
                do {
                    asm volatile("ld.acquire.gpu.u32 %0, [%1];"
                                 : "=r"(v) : "l"(bar) : "memory");
                } while (v < target);
            }
            __syncthreads();
        }
    }
}

// ---------------- tf32 output projection: out = h_final @ W^T + b ----------------
__global__ __launch_bounds__(128)
void out_gemm_kernel(const float* __restrict__ W,
                     const float* __restrict__ biasp,
                     float* __restrict__ Cout)
{
    const int tid  = threadIdx.x;
    const int lane = tid & 31;
    const int warp = tid >> 5;
    const int wm = (warp >> 1) * 64;
    const int wn = (warp & 1) * 32;
    const int n0 = blockIdx.x * BN;
    const int m0 = blockIdx.y * BM;

    __shared__ struct { float A[2][BM * AS]; float B[2][BN * BSS]; } sm;

    const float* Ain = g_h[0];
    const int kcol  = (tid & 3) * 4;
    const int ldrow = tid >> 2;

    const float* arp[4];
#pragma unroll
    for (int i = 0; i < 4; i++)
        arp[i] = Ain + (size_t)(m0 + ldrow + 32 * i) * HIDN + kcol;
    const float* brp[2];
#pragma unroll
    for (int i = 0; i < 2; i++)
        brp[i] = W + (size_t)(n0 + ldrow + 32 * i) * HIDN + kcol;

    float4 areg[4], breg[2];
    float acc[4][4][4];
#pragma unroll
    for (int a = 0; a < 4; a++)
#pragma unroll
        for (int b_ = 0; b_ < 4; b_++)
#pragma unroll
            for (int c_ = 0; c_ < 4; c_++) acc[a][b_][c_] = 0.f;

#pragma unroll
    for (int i = 0; i < 4; i++) areg[i] = *(const float4*)(arp[i]);
#pragma unroll
    for (int i = 0; i < 2; i++) breg[i] = *(const float4*)(brp[i]);
#pragma unroll
    for (int i = 0; i < 4; i++) {
        float4 v = areg[i];
        v.x = f2tf32(v.x); v.y = f2tf32(v.y); v.z = f2tf32(v.z); v.w = f2tf32(v.w);
        *(float4*)&sm.A[0][(ldrow + 32 * i) * AS + kcol] = v;
    }
#pragma unroll
    for (int i = 0; i < 2; i++) {
        float4 v = breg[i];
        v.x = f2tf32(v.x); v.y = f2tf32(v.y); v.z = f2tf32(v.z); v.w = f2tf32(v.w);
        *(float4*)&sm.B[0][(ldrow + 32 * i) * BSS + kcol] = v;
    }
    __syncthreads();

    const int NCH = HIDN / BK;
    for (int kc = 0; kc < NCH; kc++) {
        int cur = kc & 1;
        if (kc + 1 < NCH) {
#pragma unroll
            for (int i = 0; i < 4; i++) areg[i] = *(const float4*)(arp[i] + (kc + 1) * BK);
#pragma unroll
            for (int i = 0; i < 2; i++) breg[i] = *(const float4*)(brp[i] + (kc + 1) * BK);
        }
#pragma unroll
        for (int k8 = 0; k8 < BK; k8 += 8) {
            uint32_t af[4][4], bfr[4][2];
#pragma unroll
            for (int mt = 0; mt < 4; mt++) {
                const float* ap = &sm.A[cur][(wm + mt * 16 + (lane >> 2)) * AS + k8 + (lane & 3)];
                af[mt][0] = __float_as_uint(ap[0]);
                af[mt][1] = __float_as_uint(ap[8 * AS]);
                af[mt][2] = __float_as_uint(ap[4]);
                af[mt][3] = __float_as_uint(ap[8 * AS + 4]);
            }
#pragma unroll
            for (int nt = 0; nt < 4; nt++) {
                const float* bp = &sm.B[cur][(wn + nt * 8 + (lane >> 2)) * BSS + k8 + (lane & 3)];
                bfr[nt][0] = __float_as_uint(bp[0]);
                bfr[nt][1] = __float_as_uint(bp[4]);
            }
#pragma unroll
            for (int mt = 0; mt < 4; mt++)
#pragma unroll
                for (int nt = 0; nt < 4; nt++)
                    asm volatile(
                        "mma.sync.aligned.m16n8k8.row.col.f32.tf32.tf32.f32 "
                        "{%0,%1,%2,%3}, {%4,%5,%6,%7}, {%8,%9}, {%0,%1,%2,%3};"
                        : "+f"(acc[mt][nt][0]), "+f"(acc[mt][nt][1]),
                          "+f"(acc[mt][nt][2]), "+f"(acc[mt][nt][3])
                        : "r"(af[mt][0]), "r"(af[mt][1]), "r"(af[mt][2]), "r"(af[mt][3]),
                          "r"(bfr[nt][0]), "r"(bfr[nt][1]));
        }
        if (kc + 1 < NCH) {
            int nxt = cur ^ 1;
#pragma unroll
            for (int i = 0; i < 4; i++) {
                float4 v = areg[i];
                v.x = f2tf32(v.x); v.y = f2tf32(v.y); v.z = f2tf32(v.z); v.w = f2tf32(v.w);
                *(float4*)&sm.A[nxt][(ldrow + 32 * i) * AS + kcol] = v;
            }
#pragma unroll
            for (int i = 0; i < 2; i++) {
                float4 v = breg[i];
                v.x = f2tf32(v.x); v.y = f2tf32(v.y); v.z = f2tf32(v.z); v.w = f2tf32(v.w);
                *(float4*)&sm.B[nxt][(ldrow + 32 * i) * BSS + kcol] = v;
            }
        }
        __syncthreads();
    }

#pragma unroll
    for (int mt = 0; mt < 4; mt++) {
#pragma unroll
        for (int nt = 0; nt < 4; nt++) {
            int r = m0 + wm + mt * 16 + (lane >> 2);
            int cidx = n0 + wn + nt * 8 + (lane & 3) * 2;
            float2 bv = *(const float2*)&biasp[cidx];
            float2 v0; v0.x = acc[mt][nt][0] + bv.x; v0.y = acc[mt][nt][1] + bv.y;
            float2 v1; v1.x = acc[mt][nt][2] + bv.x; v1.y = acc[mt][nt][3] + bv.y;
            *(float2*)&Cout[(size_t)r * NCLS + cidx] = v0;
            *(float2*)&Cout[(size_t)(r + 8) * NCLS + cidx] = v1;
        }
    }
}

// ---------------- launch ----------------
extern "C" void kernel_launch(void* const* d_in, const int* in_sizes, int n_in,
                              void* d_out, int out_size)
{
    const int*   X   = (const int*)  d_in[0];
    const float* h0  = (const float*)d_in[1];
    const float* c0  = (const float*)d_in[2];
    const float* emb = (const float*)d_in[3];
    const float* Ui  = (const float*)d_in[4];
    const float* Vi  = (const float*)d_in[5];
    const float* bi  = (const float*)d_in[6];
    const float* Uf  = (const float*)d_in[7];
    const float* Vf  = (const float*)d_in[8];
    const float* bf  = (const float*)d_in[9];
    const float* Uc  = (const float*)d_in[10];
    const float* Vc  = (const float*)d_in[11];
    const float* bc  = (const float*)d_in[12];
    const float* Uo  = (const float*)d_in[13];
    const float* Vo  = (const float*)d_in[14];
    const float* bo  = (const float*)d_in[15];
    const float* W   = (const float*)d_in[16];
    const float* b   = (const float*)d_in[17];
    float* out = (float*)d_out;

    cudaFuncSetAttribute(lstm_persistent_kernel,
                         cudaFuncAttributeMaxDynamicSharedMemorySize, SMEM_P_BYTES);
    cudaFuncSetAttribute(input_gemm_kernel,
                         cudaFuncAttributeMaxDynamicSharedMemorySize, IG_SMEM_B);

    // 1) pack weights (bf16 interleaved), biases, init state, reset barriers
    pack_kernel<<<(NG * (HIDN / 2) + 255) / 256, 256>>>(Ui, Vi, bi, Uf, Vf, bf,
                                                        Uc, Vc, bc, Uo, Vo, bo, h0, c0);
    pack_emb_kernel<<<(int)(((size_t)NCLS * (EMBD / 2) + 255) / 256), 256>>>(emb);

    // 2) all input-side gate preactivations (cp.async 3-stage, ldmatrix)
    input_gemm_kernel<<<dim3(NG / 128, (SEQL * BATCH) / 128), 256, IG_SMEM_B>>>(X);

    // 3) all 128 recurrent steps in ONE persistent kernel (V resident, split barriers)
    lstm_persistent_kernel<<<NCTA, PTHREADS, SMEM_P_BYTES>>>();

    // 4) output projection (tf32): out = h_final @ W^T + b
    out_gemm_kernel<<<dim3(NCLS / BN, BATCH / BM), 128>>>(W, b, out);
}